// round 6
// baseline (speedup 1.0000x reference)
#include <cuda_runtime.h>
#include <cuda_bf16.h>
#include <cstdint>
#include <cfloat>
#include <math.h>

#define VV 100000
#define EE 128
#define BB 2048
#define NBX 782            // ceil(V / 128) col tiles
#define GX 18              // col-tile walkers per row block (grid 18 x 16 = 288 CTAs)
#define NP (GX * 4)        // partial slots per row
#define LROW 144           // smem row stride bytes (128B data + 16B pad)
#define ABYTES (128 * LROW)

// ---- scratch (device globals: allocation-free) ----
__device__ __align__(16) uint8_t g_emb8[BB * EE];            // fp8 e4m3, x64
__device__ __align__(16) uint8_t g_wout8[(size_t)VV * EE];   // fp8 e4m3, x64 (12.8 MB)
__device__ __align__(16) float g_ps[(size_t)BB * NP];        // sum-exp partials
__device__ float g_lse[BB];

#define INV_SCALE (1.0f / 4096.0f)

__device__ __forceinline__ uint32_t smem_u32(const void* p) {
    uint32_t a;
    asm("{ .reg .u64 t; cvta.to.shared.u64 t, %1; cvt.u32.u64 %0, t; }" : "=r"(a) : "l"(p));
    return a;
}
__device__ __forceinline__ void ldsm4(uint32_t* r, uint32_t addr) {
    asm volatile("ldmatrix.sync.aligned.m8n8.x4.shared.b16 {%0,%1,%2,%3}, [%4];"
                 : "=r"(r[0]), "=r"(r[1]), "=r"(r[2]), "=r"(r[3]) : "r"(addr));
}
__device__ __forceinline__ void cpasync16(uint32_t dst, const void* src, int src_bytes) {
    asm volatile("cp.async.cg.shared.global [%0], [%1], 16, %2;"
                 :: "r"(dst), "l"(src), "r"(src_bytes));
}
__device__ __forceinline__ uint16_t fp8x2(float lo, float hi) {
    uint16_t r;
    asm("cvt.rn.satfinite.e4m3x2.f32 %0, %1, %2;" : "=h"(r) : "f"(hi), "f"(lo));
    return r;
}

// ---- K0: W_out fp32 -> fp8 (x64) ----
__global__ void convert_wout8(const float* __restrict__ w) {
    int n4 = VV * EE / 4;
    for (int i = blockIdx.x * blockDim.x + threadIdx.x; i < n4; i += gridDim.x * blockDim.x) {
        float4 v = ((const float4*)w)[i];
        uint32_t lo = fp8x2(v.x * 64.f, v.y * 64.f);
        uint32_t hi = fp8x2(v.z * 64.f, v.w * 64.f);
        ((uint32_t*)g_wout8)[i] = lo | (hi << 16);
    }
}

// ---- K1: emb gather + bias -> fp8 (x64) ----
__global__ void gather_emb8(const void* __restrict__ cw_raw,
                            const float* __restrict__ Wc,
                            const float* __restrict__ bc) {
    int i = blockIdx.x * blockDim.x + threadIdx.x;
    if (i >= BB * EE / 4) return;
    const int* w = (const int*)cw_raw;
    bool is64 = ((w[1] | w[3] | w[5] | w[7] | w[9] | w[11] | w[13] | w[15]) == 0);
    int b = i >> 5, e0 = (i & 31) * 4;
    int idx = is64 ? w[2 * b] : w[b];
    float f[4];
    #pragma unroll
    for (int j = 0; j < 4; j++)
        f[j] = (Wc[(size_t)(e0 + j) * VV + idx] + bc[e0 + j]) * 64.f;
    uint32_t lo = fp8x2(f[0], f[1]);
    uint32_t hi = fp8x2(f[2], f[3]);
    ((uint32_t*)g_emb8)[i] = lo | (hi << 16);
}

// ---- K2: persistent fp8 GEMM; pass1 = sum-exp partials, pass2 = out = logit - lse ----
__global__ __launch_bounds__(256, 2) void gemm_fp8(const float* __restrict__ b_out,
                                                   float* __restrict__ out, int pass) {
    extern __shared__ uint8_t sm[];
    uint8_t* As = sm;                          // 128 x 144
    uint8_t* Bs0 = sm + ABYTES;                // stage 0
    uint8_t* Bs1 = sm + 2 * ABYTES;            // stage 1

    const int gx = blockIdx.x;                 // 0..17
    const int rb = blockIdx.y;                 // 0..15
    const int tid = threadIdx.x;
    const int warp = tid >> 5, lane = tid & 31;
    const int wm = warp >> 2, wn = warp & 3;
    const int g = lane >> 2, q = lane & 3;

    const uint32_t sA = smem_u32(As);
    const uint32_t sB[2] = { smem_u32(Bs0), smem_u32(Bs1) };

    // per-thread load slots: 4 x 16B chunks (1024 chunks total)
    int lr[4], lc[4];
    #pragma unroll
    for (int it = 0; it < 4; it++) {
        int chunk = it * 256 + tid;
        lr[it] = chunk >> 3;
        lc[it] = (chunk & 7) * 16;
    }

    // prologue: A (once) + B tile gx into stage 0, one commit group
    #pragma unroll
    for (int it = 0; it < 4; it++)
        cpasync16(sA + lr[it] * LROW + lc[it],
                  &g_emb8[(size_t)(rb * 128 + lr[it]) * 128 + lc[it]], 16);
    #pragma unroll
    for (int it = 0; it < 4; it++) {
        int v = gx * 128 + lr[it];
        cpasync16(sB[0] + lr[it] * LROW + lc[it],
                  &g_wout8[(size_t)(v < VV ? v : 0) * 128 + lc[it]], (v < VV) ? 16 : 0);
    }
    asm volatile("cp.async.commit_group;");

    // fragment addressing (b16 units; row stride LROW bytes)
    const int arow = wm * 64 + (lane & 15);
    const int brow = wn * 32 + ((lane >> 4) << 3) + (lane & 7);
    const int acolu = (lane >> 4) * 8;
    const int bcolu = ((lane >> 3) & 1) * 8;

    // preload A fragments? A stays in smem; reload per tile via LDSM (cheap).
    // pass-specific prep
    float rs[4][2];   // pass1 running sum-exp per (mi, rg)
    float lsev[4][2]; // pass2 per-row lse
    #pragma unroll
    for (int mi = 0; mi < 4; mi++)
        #pragma unroll
        for (int rg = 0; rg < 2; rg++) {
            rs[mi][rg] = 0.f;
            if (pass == 2)
                lsev[mi][rg] = g_lse[rb * 128 + wm * 64 + mi * 16 + rg * 8 + g];
        }

    int stage = 0;
    for (int nt = gx; nt < NBX; nt += GX, stage ^= 1) {
        int ntn = nt + GX;
        if (ntn < NBX) {
            #pragma unroll
            for (int it = 0; it < 4; it++) {
                int v = ntn * 128 + lr[it];
                cpasync16(sB[stage ^ 1] + lr[it] * LROW + lc[it],
                          &g_wout8[(size_t)(v < VV ? v : 0) * 128 + lc[it]],
                          (v < VV) ? 16 : 0);
            }
            asm volatile("cp.async.commit_group;");
            asm volatile("cp.async.wait_group 1;");
        } else {
            asm volatile("cp.async.wait_group 0;");
        }
        __syncthreads();

        const uint32_t sBc = sB[stage];
        float acc[4][4][4];
        #pragma unroll
        for (int a = 0; a < 4; a++)
            #pragma unroll
            for (int b = 0; b < 4; b++)
                #pragma unroll
                for (int c = 0; c < 4; c++) acc[a][b][c] = 0.f;

        #pragma unroll
        for (int kk = 0; kk < 4; kk++) {
            uint32_t af[4][4], bf[2][4];
            #pragma unroll
            for (int mi = 0; mi < 4; mi++)
                ldsm4(af[mi], sA + (arow + mi * 16) * LROW + (kk * 16 + acolu) * 2);
            #pragma unroll
            for (int gi = 0; gi < 2; gi++)
                ldsm4(bf[gi], sBc + (brow + gi * 16) * LROW + (kk * 16 + bcolu) * 2);
            #pragma unroll
            for (int mi = 0; mi < 4; mi++)
                #pragma unroll
                for (int ni = 0; ni < 4; ni++) {
                    uint32_t b0 = bf[ni >> 1][(ni & 1) * 2];
                    uint32_t b1 = bf[ni >> 1][(ni & 1) * 2 + 1];
                    asm volatile(
                        "mma.sync.aligned.m16n8k32.row.col.f32.e4m3.e4m3.f32 "
                        "{%0,%1,%2,%3}, {%4,%5,%6,%7}, {%8,%9}, {%0,%1,%2,%3};"
                        : "+f"(acc[mi][ni][0]), "+f"(acc[mi][ni][1]),
                          "+f"(acc[mi][ni][2]), "+f"(acc[mi][ni][3])
                        : "r"(af[mi][0]), "r"(af[mi][1]), "r"(af[mi][2]), "r"(af[mi][3]),
                          "r"(b0), "r"(b1));
                }
        }

        // epilogue
        float bo[4][2]; int cols[4];
        bool full = (nt * 128 + 128 <= VV);
        #pragma unroll
        for (int ni = 0; ni < 4; ni++) {
            int col = nt * 128 + wn * 32 + ni * 8 + q * 2;
            cols[ni] = col;
            bool ok = full || (col < VV);
            bo[ni][0] = ok ? b_out[col]     : 0.f;
            bo[ni][1] = ok ? b_out[col + 1] : 0.f;
        }

        if (pass == 1) {
            #pragma unroll
            for (int mi = 0; mi < 4; mi++)
                #pragma unroll
                for (int rg = 0; rg < 2; rg++) {
                    float s = 0.f;
                    #pragma unroll
                    for (int ni = 0; ni < 4; ni++) {
                        if (full || cols[ni] < VV) {
                            s += __expf(fmaf(acc[mi][ni][rg * 2 + 0], INV_SCALE, bo[ni][0]));
                            s += __expf(fmaf(acc[mi][ni][rg * 2 + 1], INV_SCALE, bo[ni][1]));
                        }
                    }
                    rs[mi][rg] += s;
                }
        } else {
            #pragma unroll
            for (int mi = 0; mi < 4; mi++)
                #pragma unroll
                for (int rg = 0; rg < 2; rg++) {
                    int grow = rb * 128 + wm * 64 + mi * 16 + rg * 8 + g;
                    float l = lsev[mi][rg];
                    float* op = out + (size_t)grow * VV;
                    #pragma unroll
                    for (int ni = 0; ni < 4; ni++) {
                        if (full || cols[ni] < VV) {
                            float2 o;
                            o.x = fmaf(acc[mi][ni][rg * 2 + 0], INV_SCALE, bo[ni][0]) - l;
                            o.y = fmaf(acc[mi][ni][rg * 2 + 1], INV_SCALE, bo[ni][1]) - l;
                            *(float2*)&op[cols[ni]] = o;
                        }
                    }
                }
        }
        __syncthreads();   // protect buf[stage] before it is refilled next+1 iter
    }

    if (pass == 1) {
        #pragma unroll
        for (int mi = 0; mi < 4; mi++)
            #pragma unroll
            for (int rg = 0; rg < 2; rg++) {
                float s = rs[mi][rg];
                s += __shfl_xor_sync(0xffffffffu, s, 1);
                s += __shfl_xor_sync(0xffffffffu, s, 2);
                if (q == 0) {
                    int grow = rb * 128 + wm * 64 + mi * 16 + rg * 8 + g;
                    g_ps[(size_t)grow * NP + gx * 4 + wn] = s;
                }
            }
    }
}

// ---- K3: lse[row] = log(sum of partials) ----
__global__ void reduce_lse() {
    int row = blockIdx.x;
    int tid = threadIdx.x;   // 128
    float s = (tid < NP) ? g_ps[(size_t)row * NP + tid] : 0.f;
    __shared__ float ss_[128];
    ss_[tid] = s;
    __syncthreads();
    for (int off = 64; off > 0; off >>= 1) {
        if (tid < off) ss_[tid] += ss_[tid + off];
        __syncthreads();
    }
    if (tid == 0) g_lse[row] = logf(ss_[0]);
}

extern "C" void kernel_launch(void* const* d_in, const int* in_sizes, int n_in,
                              void* d_out, int out_size) {
    const void*  cw = d_in[0];
    const float* Wc = (const float*)d_in[1];
    const float* bc = (const float*)d_in[2];
    const float* Wo = (const float*)d_in[3];
    const float* bo = (const float*)d_in[4];
    float* out = (float*)d_out;

    const int smem = 3 * ABYTES;   // 55296
    cudaFuncSetAttribute(gemm_fp8, cudaFuncAttributeMaxDynamicSharedMemorySize, smem);

    convert_wout8<<<6400, 256>>>(Wo);
    gather_emb8<<<(BB * EE / 4 + 255) / 256, 256>>>(cw, Wc, bc);
    gemm_fp8<<<dim3(GX, BB / 128), 256, smem>>>(bo, out, 1);
    reduce_lse<<<BB, 128>>>();
    gemm_fp8<<<dim3(GX, BB / 128), 256, smem>>>(bo, out, 2);
}

// round 7
// speedup vs baseline: 1.0954x; 1.0954x over previous
#include <cuda_runtime.h>
#include <cuda_bf16.h>
#include <cstdint>
#include <cfloat>
#include <math.h>

#define VV 100000
#define EE 128
#define BB 2048
#define NBX 782            // ceil(V / 128) col tiles
#define NPX (NBX * 4)      // partial slots per row
#define LROW 144           // smem row stride bytes (128B data + 16B pad)

// ---- scratch (device globals: allocation-free) ----
__device__ __align__(16) uint8_t g_emb8[BB * EE];                  // fp8 e4m3, x64
__device__ __align__(16) uint8_t g_wout8[(size_t)VV * EE];         // fp8 e4m3, x64
__device__ __align__(16) __nv_bfloat16 g_logits[(size_t)BB * VV];  // 409.6 MB
__device__ __align__(16) float g_ps[(size_t)BB * NPX];             // sum-exp partials
__device__ float g_lse[BB];

#define INV_SCALE (1.0f / 4096.0f)

__device__ __forceinline__ uint32_t smem_u32(const void* p) {
    uint32_t a;
    asm("{ .reg .u64 t; cvta.to.shared.u64 t, %1; cvt.u32.u64 %0, t; }" : "=r"(a) : "l"(p));
    return a;
}
__device__ __forceinline__ void ldsm4(uint32_t* r, uint32_t addr) {
    asm volatile("ldmatrix.sync.aligned.m8n8.x4.shared.b16 {%0,%1,%2,%3}, [%4];"
                 : "=r"(r[0]), "=r"(r[1]), "=r"(r[2]), "=r"(r[3]) : "r"(addr));
}
__device__ __forceinline__ void cpasync16(uint32_t dst, const void* src, int src_bytes) {
    asm volatile("cp.async.cg.shared.global [%0], [%1], 16, %2;"
                 :: "r"(dst), "l"(src), "r"(src_bytes));
}
__device__ __forceinline__ uint16_t fp8x2(float lo, float hi) {
    uint16_t r;
    asm("cvt.rn.satfinite.e4m3x2.f32 %0, %1, %2;" : "=h"(r) : "f"(hi), "f"(lo));
    return r;
}

// ---- K0: W_out fp32 -> fp8 (x64) ----
__global__ void convert_wout8(const float* __restrict__ w) {
    int n4 = VV * EE / 4;
    for (int i = blockIdx.x * blockDim.x + threadIdx.x; i < n4; i += gridDim.x * blockDim.x) {
        float4 v = ((const float4*)w)[i];
        uint32_t lo = fp8x2(v.x * 64.f, v.y * 64.f);
        uint32_t hi = fp8x2(v.z * 64.f, v.w * 64.f);
        ((uint32_t*)g_wout8)[i] = lo | (hi << 16);
    }
}

// ---- K1: emb gather + bias -> fp8 (x64) ----
__global__ void gather_emb8(const void* __restrict__ cw_raw,
                            const float* __restrict__ Wc,
                            const float* __restrict__ bc) {
    int i = blockIdx.x * blockDim.x + threadIdx.x;
    if (i >= BB * EE / 4) return;
    const int* w = (const int*)cw_raw;
    bool is64 = ((w[1] | w[3] | w[5] | w[7] | w[9] | w[11] | w[13] | w[15]) == 0);
    int b = i >> 5, e0 = (i & 31) * 4;
    int idx = is64 ? w[2 * b] : w[b];
    float f[4];
    #pragma unroll
    for (int j = 0; j < 4; j++)
        f[j] = (Wc[(size_t)(e0 + j) * VV + idx] + bc[e0 + j]) * 64.f;
    uint32_t lo = fp8x2(f[0], f[1]);
    uint32_t hi = fp8x2(f[2], f[3]);
    ((uint32_t*)g_emb8)[i] = lo | (hi << 16);
}

// ---- K2: fp8 GEMM 128x128xK128; writes bf16 logits + sum-exp partials (shift 0) ----
__global__ __launch_bounds__(256, 2) void gemm_fp8(const float* __restrict__ b_out) {
    extern __shared__ uint8_t sm[];
    uint8_t* As = sm;                 // 128 x 144
    uint8_t* Bs = sm + 128 * LROW;

    const int bx = blockIdx.x, by = blockIdx.y;
    const int tid = threadIdx.x;
    const int warp = tid >> 5, lane = tid & 31;
    const int wm = warp >> 2, wn = warp & 3;
    const int g = lane >> 2, q = lane & 3;

    const uint32_t sA = smem_u32(As);
    const uint32_t sB = smem_u32(Bs);

    // cooperative loads: 1024 16B chunks per matrix
    #pragma unroll
    for (int it = 0; it < 4; it++) {
        int chunk = it * 256 + tid;
        int r = chunk >> 3;
        int c = (chunk & 7) * 16;
        cpasync16(sA + r * LROW + c, &g_emb8[(size_t)(by * 128 + r) * 128 + c], 16);
        int v = bx * 128 + r;
        cpasync16(sB + r * LROW + c, &g_wout8[(size_t)(v < VV ? v : 0) * 128 + c],
                  (v < VV) ? 16 : 0);
    }
    asm volatile("cp.async.commit_group;");
    asm volatile("cp.async.wait_group 0;");
    __syncthreads();

    float acc[4][4][4];
    #pragma unroll
    for (int a = 0; a < 4; a++)
        #pragma unroll
        for (int b = 0; b < 4; b++)
            #pragma unroll
            for (int c = 0; c < 4; c++) acc[a][b][c] = 0.f;

    const int arow = wm * 64 + (lane & 15);
    const int brow = wn * 32 + ((lane >> 4) << 3) + (lane & 7);
    const int acolu = (lane >> 4) * 8;
    const int bcolu = ((lane >> 3) & 1) * 8;

    #pragma unroll
    for (int kk = 0; kk < 4; kk++) {
        uint32_t af[4][4], bf[2][4];
        #pragma unroll
        for (int mi = 0; mi < 4; mi++)
            ldsm4(af[mi], sA + (arow + mi * 16) * LROW + (kk * 16 + acolu) * 2);
        #pragma unroll
        for (int gi = 0; gi < 2; gi++)
            ldsm4(bf[gi], sB + (brow + gi * 16) * LROW + (kk * 16 + bcolu) * 2);
        #pragma unroll
        for (int mi = 0; mi < 4; mi++)
            #pragma unroll
            for (int ni = 0; ni < 4; ni++) {
                uint32_t b0 = bf[ni >> 1][(ni & 1) * 2];
                uint32_t b1 = bf[ni >> 1][(ni & 1) * 2 + 1];
                asm volatile(
                    "mma.sync.aligned.m16n8k32.row.col.f32.e4m3.e4m3.f32 "
                    "{%0,%1,%2,%3}, {%4,%5,%6,%7}, {%8,%9}, {%0,%1,%2,%3};"
                    : "+f"(acc[mi][ni][0]), "+f"(acc[mi][ni][1]),
                      "+f"(acc[mi][ni][2]), "+f"(acc[mi][ni][3])
                    : "r"(af[mi][0]), "r"(af[mi][1]), "r"(af[mi][2]), "r"(af[mi][3]),
                      "r"(b0), "r"(b1));
            }
    }

    // bias per column pair
    float bo[4][2]; bool okc[4]; int cols[4];
    #pragma unroll
    for (int ni = 0; ni < 4; ni++) {
        int col = bx * 128 + wn * 32 + ni * 8 + q * 2;
        cols[ni] = col;
        okc[ni] = (col < VV);
        bo[ni][0] = okc[ni] ? b_out[col]     : 0.f;
        bo[ni][1] = okc[ni] ? b_out[col + 1] : 0.f;
    }

    // epilogue: bf16 logits store + running sum-exp (fixed shift 0; logits are O(1))
    float rs[4][2];
    #pragma unroll
    for (int mi = 0; mi < 4; mi++) {
        #pragma unroll
        for (int rg = 0; rg < 2; rg++) {
            int grow = by * 128 + wm * 64 + mi * 16 + rg * 8 + g;
            __nv_bfloat16* lp = g_logits + (size_t)grow * VV;
            float s = 0.f;
            #pragma unroll
            for (int ni = 0; ni < 4; ni++) {
                if (okc[ni]) {
                    float v0 = fmaf(acc[mi][ni][rg * 2 + 0], INV_SCALE, bo[ni][0]);
                    float v1 = fmaf(acc[mi][ni][rg * 2 + 1], INV_SCALE, bo[ni][1]);
                    *(__nv_bfloat162*)&lp[cols[ni]] = __floats2bfloat162_rn(v0, v1);
                    s += __expf(v0) + __expf(v1);
                }
            }
            rs[mi][rg] = s;
        }
    }
    #pragma unroll
    for (int mi = 0; mi < 4; mi++)
        #pragma unroll
        for (int rg = 0; rg < 2; rg++) {
            float s = rs[mi][rg];
            s += __shfl_xor_sync(0xffffffffu, s, 1);
            s += __shfl_xor_sync(0xffffffffu, s, 2);
            if (q == 0) {
                int grow = by * 128 + wm * 64 + mi * 16 + rg * 8 + g;
                g_ps[(size_t)grow * NPX + bx * 4 + wn] = s;
            }
        }
}

// ---- K3: lse[row] = log(sum of partials) ----
__global__ void reduce_lse() {
    int row = blockIdx.x;
    int tid = threadIdx.x;   // 256
    float s = 0.f;
    const float* p = &g_ps[(size_t)row * NPX];
    for (int j = tid; j < NPX; j += 256) s += p[j];
    __shared__ float ss_[256];
    ss_[tid] = s;
    __syncthreads();
    for (int off = 128; off > 0; off >>= 1) {
        if (tid < off) ss_[tid] += ss_[tid + off];
        __syncthreads();
    }
    if (tid == 0) g_lse[row] = logf(ss_[0]);
}

// ---- K4: out = bf16_logits - lse (read 409MB, write 819MB) ----
__global__ void finalize(float* __restrict__ out) {
    int j = blockIdx.x * blockDim.x + threadIdx.x;   // uint4 chunk (8 bf16)
    int row = blockIdx.y;
    const int nch = VV / 8;  // 12500
    if (j < nch) {
        float l = g_lse[row];
        uint4 v = *(const uint4*)(g_logits + (size_t)row * VV + j * 8);
        const __nv_bfloat162* p = (const __nv_bfloat162*)&v;
        float* op = out + (size_t)row * VV + j * 8;
        float4 o0, o1;
        float2 f;
        f = __bfloat1622float2(p[0]); o0.x = f.x - l; o0.y = f.y - l;
        f = __bfloat1622float2(p[1]); o0.z = f.x - l; o0.w = f.y - l;
        f = __bfloat1622float2(p[2]); o1.x = f.x - l; o1.y = f.y - l;
        f = __bfloat1622float2(p[3]); o1.z = f.x - l; o1.w = f.y - l;
        ((float4*)op)[0] = o0;
        ((float4*)op)[1] = o1;
    }
}

extern "C" void kernel_launch(void* const* d_in, const int* in_sizes, int n_in,
                              void* d_out, int out_size) {
    const void*  cw = d_in[0];
    const float* Wc = (const float*)d_in[1];
    const float* bc = (const float*)d_in[2];
    const float* Wo = (const float*)d_in[3];
    const float* bo = (const float*)d_in[4];
    float* out = (float*)d_out;

    const int smem = 2 * 128 * LROW;   // 36864
    cudaFuncSetAttribute(gemm_fp8, cudaFuncAttributeMaxDynamicSharedMemorySize, smem);

    convert_wout8<<<6400, 256>>>(Wo);
    gather_emb8<<<(BB * EE / 4 + 255) / 256, 256>>>(cw, Wc, bc);
    gemm_fp8<<<dim3(NBX, BB / 128), 256, smem>>>(bo);
    reduce_lse<<<BB, 256>>>();
    finalize<<<dim3((VV / 8 + 255) / 256, BB), 256>>>(out);
}